// round 5
// baseline (speedup 1.0000x reference)
#include <cuda_runtime.h>
#include <cuda_bf16.h>
#include <cstdint>
#include <math.h>

// ---------------- problem sizes ----------------
#define NB 4
#define LL 128
#define HH 256
#define HD2 512
#define HD4 1024
#define CN 6
#define EMBD 400
#define GEND 300
#define NROWS 512            // B*L
#define AUGW 1056            // 4H + 3C = 1042, padded to multiple of 16

// ---------------- scratch (no cudaMalloc allowed) ----------------
__device__ float g_emb[NROWS*EMBD];
__device__ float g_bsumf[HD4];
__device__ float g_bsumb[HD4];
__device__ float g_gxf[NROWS*HD4];
__device__ float g_gxb[NROWS*HD4];
__device__ float g_ctx[NROWS*HD2];
__device__ float g_q[NROWS*HD2];
__device__ float g_k[NROWS*HD2];
__device__ float g_scores[NB*LL*LL];
__device__ float g_ctx2[NROWS*HD2];
__device__ float g_a[NROWS*CN];
__device__ float g_v[NROWS*CN];
__device__ float g_lm[NROWS*CN];
__device__ float g_augR[NROWS*AUGW];
__device__ float g_augC[NROWS*AUGW];
__device__ float g_FR[NROWS*HD4];
__device__ float g_FC[NROWS*HD4];
__device__ float g_fwpad[HD4*AUGW];

__device__ __forceinline__ float sigmoidf_(float x) { return 1.f / (1.f + expf(-x)); }

__device__ __forceinline__ uint32_t smem_u32_(const void* p) {
    uint32_t a;
    asm("{ .reg .u64 t; cvta.to.shared.u64 t, %1; cvt.u32.u64 %0, t; }" : "=r"(a) : "l"(p));
    return a;
}
__device__ __forceinline__ void st_dsmem_f32_(uint32_t saddr, int rank, float v) {
    uint32_t ra;
    asm volatile("mapa.shared::cluster.u32 %0, %1, %2;" : "=r"(ra) : "r"(saddr), "r"(rank));
    asm volatile("st.shared::cluster.f32 [%0], %1;" :: "r"(ra), "f"(v) : "memory");
}
__device__ __forceinline__ void cluster_sync_() {
    asm volatile("barrier.cluster.arrive.aligned;" ::: "memory");
    asm volatile("barrier.cluster.wait.aligned;" ::: "memory");
}

// ---------------- tiny prep kernels ----------------
__global__ void bias_sum_kernel(const float* __restrict__ bihf, const float* __restrict__ bhhf,
                                const float* __restrict__ bihb, const float* __restrict__ bhhb) {
    int i = blockIdx.x * blockDim.x + threadIdx.x;
    if (i < HD4) {
        g_bsumf[i] = bihf[i] + bhhf[i];
        g_bsumb[i] = bihb[i] + bhhb[i];
    }
}

__global__ void fwpad_kernel(const float* __restrict__ feat_w) {
    int n = blockIdx.x;
    for (int k = threadIdx.x; k < AUGW; k += blockDim.x)
        g_fwpad[n*AUGW + k] = (k < 1042) ? feat_w[n*1042 + k] : 0.f;
}

__global__ void embed_kernel(const int* __restrict__ tok, const float* __restrict__ mask,
                             const float* __restrict__ gen, const float* __restrict__ dom) {
    int r = blockIdx.x;
    int t = tok[r];
    float m = mask[r];
    const float* gp = gen + (size_t)t * GEND;
    const float* dp = dom + (size_t)t * (EMBD - GEND);
    for (int d = threadIdx.x; d < EMBD; d += blockDim.x)
        g_emb[r*EMBD + d] = m * (d < GEND ? gp[d] : dp[d - GEND]);
}

// ---------------- generic fp32 GEMM: C[M,N] = A[M,K] * W[N,K]^T (+bias) --------------
// K multiple of 16; M,N multiples of 64. grid (M/64, N/64, Z).
__launch_bounds__(256)
__global__ void sgemm_kernel(const float* __restrict__ A, int lda, long aB,
                             const float* __restrict__ W, int ldb, long wB,
                             const float* __restrict__ bias,
                             float* __restrict__ C, int ldc, long cB,
                             int K)
{
    A += (long)blockIdx.z * aB; W += (long)blockIdx.z * wB; C += (long)blockIdx.z * cB;
    __shared__ float As[16][68];
    __shared__ float Bs[16][68];
    const int tid = threadIdx.x;
    const int tx = tid & 15, ty = tid >> 4;
    const int m0 = blockIdx.x * 64, n0 = blockIdx.y * 64;
    float acc[4][4];
#pragma unroll
    for (int i = 0; i < 4; i++)
#pragma unroll
        for (int j = 0; j < 4; j++) acc[i][j] = 0.f;

    for (int k0 = 0; k0 < K; k0 += 16) {
#pragma unroll
        for (int i = 0; i < 4; i++) {
            int idx = tid + i * 256;
            int m = idx >> 4, kk = idx & 15;
            As[kk][m] = A[(size_t)(m0 + m) * lda + k0 + kk];
            Bs[kk][m] = W[(size_t)(n0 + m) * ldb + k0 + kk];
        }
        __syncthreads();
#pragma unroll
        for (int kk = 0; kk < 16; kk++) {
            float4 a4 = *(const float4*)&As[kk][ty * 4];
            float4 b4 = *(const float4*)&Bs[kk][tx * 4];
            float av[4] = {a4.x, a4.y, a4.z, a4.w};
            float bv[4] = {b4.x, b4.y, b4.z, b4.w};
#pragma unroll
            for (int i = 0; i < 4; i++)
#pragma unroll
                for (int j = 0; j < 4; j++)
                    acc[i][j] = fmaf(av[i], bv[j], acc[i][j]);
        }
        __syncthreads();
    }
#pragma unroll
    for (int i = 0; i < 4; i++) {
        int m = m0 + ty * 4 + i;
        float4 o = make_float4(acc[i][0], acc[i][1], acc[i][2], acc[i][3]);
        if (bias) {
            const float* bp = bias + n0 + tx * 4;
            o.x += bp[0]; o.y += bp[1]; o.z += bp[2]; o.w += bp[3];
        }
        *(float4*)&C[(size_t)m * ldc + n0 + tx * 4] = o;
    }
}

// ---------------- BiLSTM: one 8-CTA cluster per direction ----------------
// grid (8, 2), cluster (8,1,1). CTA rank r owns hidden units [32r, 32r+32).
// whh slice (128 gate rows x 256) SMEM-resident. Per step: compute gates from
// local h buffer, cell update, push own h slice into every rank's next-parity
// h buffer via DSMEM, one hardware cluster barrier. No spin locks anywhere.
#define LSTM_SMEM_FLOATS (128*260 + 2*4*260 + 4*128 + 4*32)

__global__ void __launch_bounds__(512, 1) __cluster_dims__(8, 1, 1)
lstm_kernel(const float* __restrict__ whh_f, const float* __restrict__ whh_b) {
    extern __shared__ float sm[];
    float* Wsm = sm;                        // [128][260]
    float* hsm = Wsm + 128*260;             // [2][4][260]
    float* gsm = hsm + 2*4*260;             // [4][128]
    float* cst = gsm + 4*128;               // [4][32]
    const int dir  = blockIdx.y;
    const int rank = blockIdx.x;            // == cluster rank (cluster spans x)
    const int base = rank * 32;
    const float* whh = dir ? whh_b : whh_f;
    const float* gx  = dir ? g_gxb : g_gxf;
    const int tid = threadIdx.x;

    // load whh slice: local row lr -> global gate row ((lr>>5)<<8) + base + (lr&31)
    for (int i = tid; i < 128*256; i += 512) {
        int lr = i >> 8, k = i & 255;
        int grow = ((lr >> 5) << 8) + base + (lr & 31);
        Wsm[lr*260 + k] = whh[grow*256 + k];
    }
    // zero both h parity buffers + cell state
    for (int i = tid; i < 2*4*260; i += 512) hsm[i] = 0.f;
    if (tid < 128) cst[tid] = 0.f;
    __syncthreads();
    cluster_sync_();   // peers must not receive DSMEM h before buffers are zeroed

    const int b  = tid & 3;
    const int lr = tid >> 2;
    const int grow = ((lr >> 5) << 8) + base + (lr & 31);
    const uint32_t hsm_sa = smem_u32_(hsm);
    int par = 0;

    for (int step = 0; step < 128; step++) {
        const int pos = dir ? (127 - step) : step;

        float a0 = 0.f, a1 = 0.f, a2 = 0.f, a3 = 0.f;
        const float4* wr = (const float4*)(Wsm + lr*260);
        const float4* hr = (const float4*)(hsm + (par*4 + b)*260);
#pragma unroll 8
        for (int kk = 0; kk < 64; kk++) {
            float4 w = wr[kk], h = hr[kk];
            a0 = fmaf(w.x, h.x, a0);
            a1 = fmaf(w.y, h.y, a1);
            a2 = fmaf(w.z, h.z, a2);
            a3 = fmaf(w.w, h.w, a3);
        }
        gsm[b*128 + lr] = gx[(((size_t)((b << 7) + pos)) << 10) + grow] + ((a0 + a1) + (a2 + a3));
        __syncthreads();

        if (tid < 128) {
            int u = tid >> 2, bb = tid & 3;
            float gi = gsm[bb*128 + u];
            float gf = gsm[bb*128 + 32 + u];
            float gg = gsm[bb*128 + 64 + u];
            float go = gsm[bb*128 + 96 + u];
            float c = sigmoidf_(gf) * cst[bb*32 + u] + sigmoidf_(gi) * tanhf(gg);
            float h = sigmoidf_(go) * tanhf(c);
            cst[bb*32 + u] = c;
            g_ctx[(((size_t)((bb << 7) + pos)) << 9) + (dir << 8) + base + u] = h;
            // broadcast h into every rank's next-parity buffer (incl. self)
            uint32_t off = hsm_sa + (((par ^ 1)*4 + bb)*260 + base + u) * 4u;
#pragma unroll
            for (int rdst = 0; rdst < 8; rdst++)
                st_dsmem_f32_(off, rdst, h);
        }
        cluster_sync_();   // all DSMEM h writes visible cluster-wide
        par ^= 1;
    }
}

// ---------------- softmax over last dim (128) ----------------
__global__ void softmax_kernel() {
    int r = blockIdx.x, t = threadIdx.x;
    __shared__ float red[128];
    float x = g_scores[(r << 7) + t];
    red[t] = x; __syncthreads();
    for (int off = 64; off; off >>= 1) { if (t < off) red[t] = fmaxf(red[t], red[t + off]); __syncthreads(); }
    float m = red[0]; __syncthreads();
    float e = expf(x - m);
    red[t] = e; __syncthreads();
    for (int off = 64; off; off >>= 1) { if (t < off) red[t] += red[t + off]; __syncthreads(); }
    g_scores[(r << 7) + t] = e / red[0];
}

// ---------------- ctx2 = ctx + attn @ ctx ----------------
__global__ void av_kernel() {
    int r = blockIdx.x;          // b*128 + i
    int b = r >> 7;
    int n = threadIdx.x;         // 0..127
    __shared__ float arow[128];
    arow[n] = g_scores[(r << 7) + n];
    __syncthreads();
    float acc0 = 0.f, acc1 = 0.f, acc2 = 0.f, acc3 = 0.f;
    for (int k = 0; k < 128; k++) {
        float a = arow[k];
        const float* cr = g_ctx + (((size_t)((b << 7) + k)) << 9);
        acc0 = fmaf(a, cr[n],       acc0);
        acc1 = fmaf(a, cr[n + 128], acc1);
        acc2 = fmaf(a, cr[n + 256], acc2);
        acc3 = fmaf(a, cr[n + 384], acc3);
    }
    const float* crr = g_ctx + ((size_t)r << 9);
    float* o = g_ctx2 + ((size_t)r << 9);
    o[n]       = crr[n]       + acc0;
    o[n + 128] = crr[n + 128] + acc1;
    o[n + 256] = crr[n + 256] + acc2;
    o[n + 384] = crr[n + 384] + acc3;
}

// ---------------- class projection: Y[r,c] = X[r, :K] . cls_w[c, wOff:wOff+K] (+bias) ----
__global__ void proj6_kernel(const float* __restrict__ X, int lda, int wOff, int K,
                             const float* __restrict__ cw, const float* __restrict__ bias,
                             float* __restrict__ Y) {
    int r = blockIdx.x;
    int c = threadIdx.x >> 5, l = threadIdx.x & 31;
    const float* xr = X + (size_t)r * lda;
    const float* wr = cw + c * 1024 + wOff;
    float acc = 0.f;
    for (int k = l; k < K; k += 32) acc = fmaf(xr[k], wr[k], acc);
#pragma unroll
    for (int off = 16; off; off >>= 1) acc += __shfl_xor_sync(0xffffffffu, acc, off);
    if (l == 0) Y[r*CN + c] = acc + (bias ? bias[c] : 0.f);
}

// ---------------- lm scan: prefix/suffix max per (b,c) ----------------
__global__ void lm_kernel() {
    __shared__ float sa[128], sv[128], pa[128], sf[128];
    int t = threadIdx.x;
    int b = blockIdx.x / CN, c = blockIdx.x % CN;
    float av = g_a[((b << 7) + t)*CN + c];
    float vv = g_v[((b << 7) + t)*CN + c];
    sa[t] = av; sv[t] = vv; pa[t] = av; sf[t] = vv;
    __syncthreads();
    for (int off = 1; off < 128; off <<= 1) {
        float nx = pa[t]; if (t >= off) nx = fmaxf(nx, pa[t - off]);
        float ny = sf[t]; if (t + off < 128) ny = fmaxf(ny, sf[t + off]);
        __syncthreads();
        pa[t] = nx; sf[t] = ny;
        __syncthreads();
    }
    float lm = fmaxf(fmaxf(pa[t] + sv[t], sa[t] + sf[t]), 0.f);
    g_lm[((b << 7) + t)*CN + c] = lm;
}

// ---------------- build augmented GEMM inputs ----------------
__global__ void aug_kernel(int mode) {
    int r = blockIdx.x;
    float* AR = g_augR + (size_t)r * AUGW;
    float* AC = g_augC + (size_t)r * AUGW;
    const float* lm = g_lm + r*CN;
    const float* aa = g_a  + r*CN;
    const float* vv = g_v  + r*CN;
    for (int k = threadIdx.x; k < AUGW; k += blockDim.x) {
        float rv = 0.f, cv = 0.f;
        if (k < 1024) {
            if (mode == 0) {
                if (k < 512) rv = g_ctx2[(size_t)r*512 + k];
                else         cv = g_ctx2[(size_t)r*512 + k - 512];
            } else {
                rv = g_FR[(size_t)r*1024 + k];
                cv = g_FC[(size_t)r*1024 + k];
            }
        } else if (k < 1030) { rv = lm[k - 1024]; }
        else if (k < 1036)   { cv = lm[k - 1030]; }
        else if (k < 1042)   { rv = aa[k - 1036]; cv = vv[k - 1036]; }
        AR[k] = rv; AC[k] = cv;
    }
}

// ---------------- final output: out[b,i,j,c] = a[b,i,c] + v[b,j,c] ----------------
__global__ void out_kernel(float* __restrict__ out) {
    int r = blockIdx.x;            // b*128 + i
    int b = r >> 7;
    int t = threadIdx.x;           // 768 = 128*6
    int j = t / CN, c = t % CN;
    out[((size_t)r * 128 + j)*CN + c] = g_a[r*CN + c] + g_v[((b << 7) + j)*CN + c];
}

// ---------------- launcher ----------------
extern "C" void kernel_launch(void* const* d_in, const int* in_sizes, int n_in,
                              void* d_out, int out_size) {
    (void)in_sizes; (void)n_in; (void)out_size;
    const int*   tok    = (const int*)  d_in[0];
    const float* mask   = (const float*)d_in[2];
    const float* gen    = (const float*)d_in[3];
    const float* dom    = (const float*)d_in[4];
    const float* wih_f  = (const float*)d_in[5];
    const float* whh_f  = (const float*)d_in[6];
    const float* bih_f  = (const float*)d_in[7];
    const float* bhh_f  = (const float*)d_in[8];
    const float* wih_b  = (const float*)d_in[9];
    const float* whh_b  = (const float*)d_in[10];
    const float* bih_b  = (const float*)d_in[11];
    const float* bhh_b  = (const float*)d_in[12];
    const float* wq     = (const float*)d_in[13];
    const float* bq     = (const float*)d_in[14];
    const float* wk     = (const float*)d_in[15];
    const float* bk     = (const float*)d_in[16];
    const float* feat_w = (const float*)d_in[17];
    const float* feat_b = (const float*)d_in[18];
    const float* cls_w  = (const float*)d_in[19];
    const float* cls_b  = (const float*)d_in[20];
    float* out = (float*)d_out;

    cudaFuncSetAttribute(lstm_kernel, cudaFuncAttributeMaxDynamicSharedMemorySize,
                         LSTM_SMEM_FLOATS * (int)sizeof(float));

    float *p_emb, *p_bsumf, *p_bsumb, *p_gxf, *p_gxb, *p_ctx, *p_q, *p_k, *p_scores,
          *p_augR, *p_augC, *p_FR, *p_FC, *p_fwpad, *p_ctx2, *p_a, *p_v;
    cudaGetSymbolAddress((void**)&p_emb,    g_emb);
    cudaGetSymbolAddress((void**)&p_bsumf,  g_bsumf);
    cudaGetSymbolAddress((void**)&p_bsumb,  g_bsumb);
    cudaGetSymbolAddress((void**)&p_gxf,    g_gxf);
    cudaGetSymbolAddress((void**)&p_gxb,    g_gxb);
    cudaGetSymbolAddress((void**)&p_ctx,    g_ctx);
    cudaGetSymbolAddress((void**)&p_q,      g_q);
    cudaGetSymbolAddress((void**)&p_k,      g_k);
    cudaGetSymbolAddress((void**)&p_scores, g_scores);
    cudaGetSymbolAddress((void**)&p_ctx2,   g_ctx2);
    cudaGetSymbolAddress((void**)&p_augR,   g_augR);
    cudaGetSymbolAddress((void**)&p_augC,   g_augC);
    cudaGetSymbolAddress((void**)&p_FR,     g_FR);
    cudaGetSymbolAddress((void**)&p_FC,     g_FC);
    cudaGetSymbolAddress((void**)&p_fwpad,  g_fwpad);
    cudaGetSymbolAddress((void**)&p_a,      g_a);
    cudaGetSymbolAddress((void**)&p_v,      g_v);

    bias_sum_kernel<<<4, 256>>>(bih_f, bhh_f, bih_b, bhh_b);
    fwpad_kernel<<<HD4, 256>>>(feat_w);
    embed_kernel<<<NROWS, 128>>>(tok, mask, gen, dom);

    // gx = emb @ wih^T + (bih+bhh)
    sgemm_kernel<<<dim3(8,16,1), 256>>>(p_emb, EMBD, 0, wih_f, EMBD, 0, p_bsumf, p_gxf, HD4, 0, EMBD);
    sgemm_kernel<<<dim3(8,16,1), 256>>>(p_emb, EMBD, 0, wih_b, EMBD, 0, p_bsumb, p_gxb, HD4, 0, EMBD);

    lstm_kernel<<<dim3(8,2,1), 512, LSTM_SMEM_FLOATS * (int)sizeof(float)>>>(whh_f, whh_b);

    // attention
    sgemm_kernel<<<dim3(8,8,1), 256>>>(p_ctx, HD2, 0, wq, HD2, 0, bq, p_q, HD2, 0, HD2);
    sgemm_kernel<<<dim3(8,8,1), 256>>>(p_ctx, HD2, 0, wk, HD2, 0, bk, p_k, HD2, 0, HD2);
    sgemm_kernel<<<dim3(2,2,4), 256>>>(p_q, HD2, (long)LL*HD2, p_k, HD2, (long)LL*HD2, nullptr,
                                       p_scores, LL, (long)LL*LL, HD2);
    softmax_kernel<<<NROWS, 128>>>();
    av_kernel<<<NROWS, 128>>>();

    // hop 0 logits (factorized)
    proj6_kernel<<<NROWS, 192>>>(p_ctx2, HD2, 0,   HD2, cls_w, cls_b,  p_a);
    proj6_kernel<<<NROWS, 192>>>(p_ctx2, HD2, 512, HD2, cls_w, nullptr, p_v);

    // hop 1
    lm_kernel<<<NB*CN, 128>>>();
    aug_kernel<<<NROWS, 256>>>(0);
    sgemm_kernel<<<dim3(8,16,1), 256>>>(p_augR, AUGW, 0, p_fwpad, AUGW, 0, feat_b, p_FR, HD4, 0, AUGW);
    sgemm_kernel<<<dim3(8,16,1), 256>>>(p_augC, AUGW, 0, p_fwpad, AUGW, 0, nullptr, p_FC, HD4, 0, AUGW);
    proj6_kernel<<<NROWS, 192>>>(p_FR, HD4, 0, HD4, cls_w, cls_b,  p_a);
    proj6_kernel<<<NROWS, 192>>>(p_FC, HD4, 0, HD4, cls_w, nullptr, p_v);

    // hop 2
    lm_kernel<<<NB*CN, 128>>>();
    aug_kernel<<<NROWS, 256>>>(1);
    sgemm_kernel<<<dim3(8,16,1), 256>>>(p_augR, AUGW, 0, p_fwpad, AUGW, 0, feat_b, p_FR, HD4, 0, AUGW);
    sgemm_kernel<<<dim3(8,16,1), 256>>>(p_augC, AUGW, 0, p_fwpad, AUGW, 0, nullptr, p_FC, HD4, 0, AUGW);
    proj6_kernel<<<NROWS, 192>>>(p_FR, HD4, 0, HD4, cls_w, cls_b,  p_a);
    proj6_kernel<<<NROWS, 192>>>(p_FC, HD4, 0, HD4, cls_w, nullptr, p_v);

    out_kernel<<<NROWS, LL*CN>>>(out);
}

// round 6
// speedup vs baseline: 1.0865x; 1.0865x over previous
#include <cuda_runtime.h>
#include <cuda_bf16.h>
#include <cstdint>
#include <math.h>

// ---------------- problem sizes ----------------
#define NB 4
#define LL 128
#define HH 256
#define HD2 512
#define HD4 1024
#define CN 6
#define EMBD 400
#define GEND 300
#define NROWS 512            // B*L
#define AUGW 1056            // 4H + 3C = 1042, padded to multiple of 16

// ---------------- scratch (no cudaMalloc allowed) ----------------
__device__ float g_emb[NROWS*EMBD];
__device__ float g_bsumf[HD4];
__device__ float g_bsumb[HD4];
__device__ float g_gxf[NROWS*HD4];
__device__ float g_gxb[NROWS*HD4];
__device__ float g_ctx[NROWS*HD2];
__device__ float g_q[NROWS*HD2];
__device__ float g_k[NROWS*HD2];
__device__ float g_ctx2[NROWS*HD2];
__device__ float g_a[NROWS*CN];
__device__ float g_v[NROWS*CN];
__device__ float g_lm[NROWS*CN];
__device__ float g_aug[2*NROWS*AUGW];    // [augR ; augC]
__device__ float g_F[2*NROWS*HD4];       // [FR ; FC]
__device__ float g_fwpad[HD4*AUGW];

__device__ __forceinline__ float sigmoidf_(float x) { return 1.f / (1.f + expf(-x)); }

__device__ __forceinline__ uint32_t smem_u32_(const void* p) {
    uint32_t a;
    asm("{ .reg .u64 t; cvta.to.shared.u64 t, %1; cvt.u32.u64 %0, t; }" : "=r"(a) : "l"(p));
    return a;
}
__device__ __forceinline__ void st_dsmem_f32_(uint32_t saddr, int rank, float v) {
    uint32_t ra;
    asm volatile("mapa.shared::cluster.u32 %0, %1, %2;" : "=r"(ra) : "r"(saddr), "r"(rank));
    asm volatile("st.shared::cluster.f32 [%0], %1;" :: "r"(ra), "f"(v) : "memory");
}
__device__ __forceinline__ void cluster_sync_() {
    asm volatile("barrier.cluster.arrive.aligned;" ::: "memory");
    asm volatile("barrier.cluster.wait.aligned;" ::: "memory");
}

// ---------------- tiny prep kernels ----------------
__global__ void bias_sum_kernel(const float* __restrict__ bihf, const float* __restrict__ bhhf,
                                const float* __restrict__ bihb, const float* __restrict__ bhhb) {
    int i = blockIdx.x * blockDim.x + threadIdx.x;
    if (i < HD4) {
        g_bsumf[i] = bihf[i] + bhhf[i];
        g_bsumb[i] = bihb[i] + bhhb[i];
    }
}

__global__ void fwpad_kernel(const float* __restrict__ feat_w) {
    int n = blockIdx.x;
    for (int k = threadIdx.x; k < AUGW; k += blockDim.x)
        g_fwpad[n*AUGW + k] = (k < 1042) ? feat_w[n*1042 + k] : 0.f;
}

__global__ void embed_kernel(const int* __restrict__ tok, const float* __restrict__ mask,
                             const float* __restrict__ gen, const float* __restrict__ dom) {
    int r = blockIdx.x;
    int t = tok[r];
    float m = mask[r];
    const float* gp = gen + (size_t)t * GEND;
    const float* dp = dom + (size_t)t * (EMBD - GEND);
    for (int d = threadIdx.x; d < EMBD; d += blockDim.x)
        g_emb[r*EMBD + d] = m * (d < GEND ? gp[d] : dp[d - GEND]);
}

// ---------------- fp32 GEMM with pointer-pair batching + reg prefetch ----------------
// C[M,N] = A[M,K] * W[N,K]^T (+bias for rows < biasLimit). K mult of 16, tiles 64x64.
// blockIdx.z in {0,1} selects pointer set.
struct SPair {
    const float* A0; const float* A1;
    const float* W0; const float* W1;
    const float* b0; const float* b1;
    float* C0; float* C1;
};

__launch_bounds__(256)
__global__ void sgemm_kernel(SPair p, int lda, int ldw, int ldc, int K, int biasLimit) {
    const float* __restrict__ A    = blockIdx.z ? p.A1 : p.A0;
    const float* __restrict__ W    = blockIdx.z ? p.W1 : p.W0;
    const float* __restrict__ bias = blockIdx.z ? p.b1 : p.b0;
    float* __restrict__ C          = blockIdx.z ? p.C1 : p.C0;
    __shared__ float As[16][68];
    __shared__ float Bs[16][68];
    const int tid = threadIdx.x;
    const int tx = tid & 15, ty = tid >> 4;
    const int m0 = blockIdx.x * 64, n0 = blockIdx.y * 64;

    int lmm[4], lkk[4];
#pragma unroll
    for (int i = 0; i < 4; i++) { int idx = tid + i * 256; lmm[i] = idx >> 4; lkk[i] = idx & 15; }

    float pa[4], pb[4];
#pragma unroll
    for (int i = 0; i < 4; i++) {
        pa[i] = A[(size_t)(m0 + lmm[i]) * lda + lkk[i]];
        pb[i] = W[(size_t)(n0 + lmm[i]) * ldw + lkk[i]];
    }

    float acc[4][4];
#pragma unroll
    for (int i = 0; i < 4; i++)
#pragma unroll
        for (int j = 0; j < 4; j++) acc[i][j] = 0.f;

    for (int k0 = 0; k0 < K; k0 += 16) {
        __syncthreads();
#pragma unroll
        for (int i = 0; i < 4; i++) {
            As[lkk[i]][lmm[i]] = pa[i];
            Bs[lkk[i]][lmm[i]] = pb[i];
        }
        __syncthreads();
        if (k0 + 16 < K) {
#pragma unroll
            for (int i = 0; i < 4; i++) {
                pa[i] = A[(size_t)(m0 + lmm[i]) * lda + k0 + 16 + lkk[i]];
                pb[i] = W[(size_t)(n0 + lmm[i]) * ldw + k0 + 16 + lkk[i]];
            }
        }
#pragma unroll
        for (int kk = 0; kk < 16; kk++) {
            float4 a4 = *(const float4*)&As[kk][ty * 4];
            float4 b4 = *(const float4*)&Bs[kk][tx * 4];
            float av[4] = {a4.x, a4.y, a4.z, a4.w};
            float bv[4] = {b4.x, b4.y, b4.z, b4.w};
#pragma unroll
            for (int i = 0; i < 4; i++)
#pragma unroll
                for (int j = 0; j < 4; j++)
                    acc[i][j] = fmaf(av[i], bv[j], acc[i][j]);
        }
    }
#pragma unroll
    for (int i = 0; i < 4; i++) {
        int m = m0 + ty * 4 + i;
        float4 o = make_float4(acc[i][0], acc[i][1], acc[i][2], acc[i][3]);
        if (bias && m < biasLimit) {
            const float* bp = bias + n0 + tx * 4;
            o.x += bp[0]; o.y += bp[1]; o.z += bp[2]; o.w += bp[3];
        }
        *(float4*)&C[(size_t)m * ldc + n0 + tx * 4] = o;
    }
}

// ---------------- BiLSTM: one 8-CTA cluster per direction ----------------
#define LSTM_SMEM_FLOATS (128*260 + 2*4*260 + 4*128 + 4*32)

__global__ void __launch_bounds__(512, 1) __cluster_dims__(8, 1, 1)
lstm_kernel(const float* __restrict__ whh_f, const float* __restrict__ whh_b) {
    extern __shared__ float sm[];
    float* Wsm = sm;                        // [128][260]
    float* hsm = Wsm + 128*260;             // [2][4][260]
    float* gsm = hsm + 2*4*260;             // [4][128]
    float* cst = gsm + 4*128;               // [4][32]
    const int dir  = blockIdx.y;
    const int rank = blockIdx.x;
    const int base = rank * 32;
    const float* whh = dir ? whh_b : whh_f;
    const float* gx  = dir ? g_gxb : g_gxf;
    const int tid = threadIdx.x;

    for (int i = tid; i < 128*256; i += 512) {
        int lr = i >> 8, k = i & 255;
        int grow = ((lr >> 5) << 8) + base + (lr & 31);
        Wsm[lr*260 + k] = whh[grow*256 + k];
    }
    for (int i = tid; i < 2*4*260; i += 512) hsm[i] = 0.f;
    if (tid < 128) cst[tid] = 0.f;
    __syncthreads();
    cluster_sync_();

    const int b  = tid & 3;
    const int lr = tid >> 2;
    const int grow = ((lr >> 5) << 8) + base + (lr & 31);
    const uint32_t hsm_sa = smem_u32_(hsm);
    int par = 0;

    for (int step = 0; step < 128; step++) {
        const int pos = dir ? (127 - step) : step;

        float a0 = 0.f, a1 = 0.f, a2 = 0.f, a3 = 0.f;
        const float4* wr = (const float4*)(Wsm + lr*260);
        const float4* hr = (const float4*)(hsm + (par*4 + b)*260);
#pragma unroll 8
        for (int kk = 0; kk < 64; kk++) {
            float4 w = wr[kk], h = hr[kk];
            a0 = fmaf(w.x, h.x, a0);
            a1 = fmaf(w.y, h.y, a1);
            a2 = fmaf(w.z, h.z, a2);
            a3 = fmaf(w.w, h.w, a3);
        }
        gsm[b*128 + lr] = gx[(((size_t)((b << 7) + pos)) << 10) + grow] + ((a0 + a1) + (a2 + a3));
        __syncthreads();

        if (tid < 128) {
            int u = tid >> 2, bb = tid & 3;
            float gi = gsm[bb*128 + u];
            float gf = gsm[bb*128 + 32 + u];
            float gg = gsm[bb*128 + 64 + u];
            float go = gsm[bb*128 + 96 + u];
            float c = sigmoidf_(gf) * cst[bb*32 + u] + sigmoidf_(gi) * tanhf(gg);
            float h = sigmoidf_(go) * tanhf(c);
            cst[bb*32 + u] = c;
            g_ctx[(((size_t)((bb << 7) + pos)) << 9) + (dir << 8) + base + u] = h;
            uint32_t off = hsm_sa + (((par ^ 1)*4 + bb)*260 + base + u) * 4u;
#pragma unroll
            for (int rdst = 0; rdst < 8; rdst++)
                st_dsmem_f32_(off, rdst, h);
        }
        cluster_sync_();
        par ^= 1;
    }
}

// ---------------- fused attention: scores + softmax + AV + residual ----------------
// one CTA per row r = b*128+i; 128 threads (thread t = column j / lane n)
__global__ void __launch_bounds__(128)
attn_kernel() {
    int r = blockIdx.x, b = r >> 7, t = threadIdx.x;
    __shared__ float qs[512];
    __shared__ float sc[128];
    __shared__ float red[128];
    const float* qrow = g_q + (size_t)r * HD2;
    for (int k = t; k < 512; k += 128) qs[k] = qrow[k];
    __syncthreads();

    // s_t = q_i . k_t
    const float4* kr = (const float4*)(g_k + ((size_t)((b << 7) + t)) * HD2);
    const float4* q4 = (const float4*)qs;
    float s0 = 0.f, s1 = 0.f, s2 = 0.f, s3 = 0.f;
#pragma unroll 8
    for (int k = 0; k < 128; k++) {
        float4 kv = kr[k], qv = q4[k];
        s0 = fmaf(qv.x, kv.x, s0);
        s1 = fmaf(qv.y, kv.y, s1);
        s2 = fmaf(qv.z, kv.z, s2);
        s3 = fmaf(qv.w, kv.w, s3);
    }
    float s = (s0 + s1) + (s2 + s3);

    // softmax over 128
    red[t] = s; __syncthreads();
    for (int off = 64; off; off >>= 1) { if (t < off) red[t] = fmaxf(red[t], red[t + off]); __syncthreads(); }
    float mx = red[0]; __syncthreads();
    float e = expf(s - mx);
    red[t] = e; __syncthreads();
    for (int off = 64; off; off >>= 1) { if (t < off) red[t] += red[t + off]; __syncthreads(); }
    sc[t] = e / red[0];
    __syncthreads();

    // AV + residual
    float a0 = 0.f, a1 = 0.f, a2 = 0.f, a3 = 0.f;
    for (int j = 0; j < 128; j++) {
        float a = sc[j];
        const float* cr = g_ctx + ((size_t)((b << 7) + j)) * HD2;
        a0 = fmaf(a, cr[t],       a0);
        a1 = fmaf(a, cr[t + 128], a1);
        a2 = fmaf(a, cr[t + 256], a2);
        a3 = fmaf(a, cr[t + 384], a3);
    }
    const float* crr = g_ctx + ((size_t)r) * HD2;
    float* o = g_ctx2 + ((size_t)r) * HD2;
    o[t]       = crr[t]       + a0;
    o[t + 128] = crr[t + 128] + a1;
    o[t + 256] = crr[t + 256] + a2;
    o[t + 384] = crr[t + 384] + a3;
}

// ---------------- dual class projection: a and v in one launch ----------------
__global__ void __launch_bounds__(384)
proj_dual_kernel(const float* __restrict__ Xa, int ldxa, int offA, int Ka,
                 const float* __restrict__ Xv, int ldxv, int offV, int Kv,
                 const float* __restrict__ cw, const float* __restrict__ cb) {
    int r = blockIdx.x;
    int tid = threadIdx.x;
    int half = tid / 192;
    int t = tid % 192;
    int c = t >> 5, l = t & 31;
    const float* X = half ? (Xv + (size_t)r * ldxv) : (Xa + (size_t)r * ldxa);
    const float* wr = cw + c * 1024 + (half ? offV : offA);
    int K = half ? Kv : Ka;
    float acc = 0.f;
    for (int k = l; k < K; k += 32) acc = fmaf(X[k], wr[k], acc);
#pragma unroll
    for (int off = 16; off; off >>= 1) acc += __shfl_xor_sync(0xffffffffu, acc, off);
    if (l == 0) {
        if (half) g_v[r*CN + c] = acc;
        else      g_a[r*CN + c] = acc + cb[c];
    }
}

// ---------------- lm scan: prefix/suffix max per (b,c) ----------------
__global__ void lm_kernel() {
    __shared__ float sa[128], sv[128], pa[128], sf[128];
    int t = threadIdx.x;
    int b = blockIdx.x / CN, c = blockIdx.x % CN;
    float av = g_a[((b << 7) + t)*CN + c];
    float vv = g_v[((b << 7) + t)*CN + c];
    sa[t] = av; sv[t] = vv; pa[t] = av; sf[t] = vv;
    __syncthreads();
    for (int off = 1; off < 128; off <<= 1) {
        float nx = pa[t]; if (t >= off) nx = fmaxf(nx, pa[t - off]);
        float ny = sf[t]; if (t + off < 128) ny = fmaxf(ny, sf[t + off]);
        __syncthreads();
        pa[t] = nx; sf[t] = ny;
        __syncthreads();
    }
    float lm = fmaxf(fmaxf(pa[t] + sv[t], sa[t] + sf[t]), 0.f);
    g_lm[((b << 7) + t)*CN + c] = lm;
}

// ---------------- build augmented GEMM inputs (stacked [augR;augC]) ----------------
__global__ void aug_kernel(int mode) {
    int r = blockIdx.x;
    float* AR = g_aug + (size_t)r * AUGW;
    float* AC = g_aug + (size_t)(NROWS + r) * AUGW;
    const float* lm = g_lm + r*CN;
    const float* aa = g_a  + r*CN;
    const float* vv = g_v  + r*CN;
    for (int k = threadIdx.x; k < AUGW; k += blockDim.x) {
        float rv = 0.f, cv = 0.f;
        if (k < 1024) {
            if (mode == 0) {
                if (k < 512) rv = g_ctx2[(size_t)r*512 + k];
                else         cv = g_ctx2[(size_t)r*512 + k - 512];
            } else {
                rv = g_F[(size_t)r*1024 + k];
                cv = g_F[(size_t)(NROWS + r)*1024 + k];
            }
        } else if (k < 1030) { rv = lm[k - 1024]; }
        else if (k < 1036)   { cv = lm[k - 1030]; }
        else if (k < 1042)   { rv = aa[k - 1036]; cv = vv[k - 1036]; }
        AR[k] = rv; AC[k] = cv;
    }
}

// ---------------- final output: out[b,i,j,c] = a[b,i,c] + v[b,j,c] ----------------
__global__ void out_kernel(float* __restrict__ out) {
    int r = blockIdx.x;
    int b = r >> 7;
    int t = threadIdx.x;           // 768 = 128*6
    int j = t / CN, c = t % CN;
    out[((size_t)r * 128 + j)*CN + c] = g_a[r*CN + c] + g_v[((b << 7) + j)*CN + c];
}

// ---------------- launcher ----------------
extern "C" void kernel_launch(void* const* d_in, const int* in_sizes, int n_in,
                              void* d_out, int out_size) {
    (void)in_sizes; (void)n_in; (void)out_size;
    const int*   tok    = (const int*)  d_in[0];
    const float* mask   = (const float*)d_in[2];
    const float* gen    = (const float*)d_in[3];
    const float* dom    = (const float*)d_in[4];
    const float* wih_f  = (const float*)d_in[5];
    const float* whh_f  = (const float*)d_in[6];
    const float* bih_f  = (const float*)d_in[7];
    const float* bhh_f  = (const float*)d_in[8];
    const float* wih_b  = (const float*)d_in[9];
    const float* whh_b  = (const float*)d_in[10];
    const float* bih_b  = (const float*)d_in[11];
    const float* bhh_b  = (const float*)d_in[12];
    const float* wq     = (const float*)d_in[13];
    const float* bq     = (const float*)d_in[14];
    const float* wk     = (const float*)d_in[15];
    const float* bk     = (const float*)d_in[16];
    const float* feat_w = (const float*)d_in[17];
    const float* feat_b = (const float*)d_in[18];
    const float* cls_w  = (const float*)d_in[19];
    const float* cls_b  = (const float*)d_in[20];
    float* out = (float*)d_out;

    cudaFuncSetAttribute(lstm_kernel, cudaFuncAttributeMaxDynamicSharedMemorySize,
                         LSTM_SMEM_FLOATS * (int)sizeof(float));

    float *p_emb, *p_bsumf, *p_bsumb, *p_gxf, *p_gxb, *p_ctx, *p_q, *p_k,
          *p_ctx2, *p_aug, *p_F, *p_fwpad;
    cudaGetSymbolAddress((void**)&p_emb,    g_emb);
    cudaGetSymbolAddress((void**)&p_bsumf,  g_bsumf);
    cudaGetSymbolAddress((void**)&p_bsumb,  g_bsumb);
    cudaGetSymbolAddress((void**)&p_gxf,    g_gxf);
    cudaGetSymbolAddress((void**)&p_gxb,    g_gxb);
    cudaGetSymbolAddress((void**)&p_ctx,    g_ctx);
    cudaGetSymbolAddress((void**)&p_q,      g_q);
    cudaGetSymbolAddress((void**)&p_k,      g_k);
    cudaGetSymbolAddress((void**)&p_ctx2,   g_ctx2);
    cudaGetSymbolAddress((void**)&p_aug,    g_aug);
    cudaGetSymbolAddress((void**)&p_F,      g_F);
    cudaGetSymbolAddress((void**)&p_fwpad,  g_fwpad);

    bias_sum_kernel<<<4, 256>>>(bih_f, bhh_f, bih_b, bhh_b);
    fwpad_kernel<<<HD4, 256>>>(feat_w);
    embed_kernel<<<NROWS, 128>>>(tok, mask, gen, dom);

    // gx_f and gx_b in one launch: C = emb @ wih^T + (bih+bhh)
    {
        SPair p = { p_emb, p_emb, wih_f, wih_b, p_bsumf, p_bsumb, p_gxf, p_gxb };
        sgemm_kernel<<<dim3(8,16,2), 256>>>(p, EMBD, EMBD, HD4, EMBD, 1<<30);
    }

    lstm_kernel<<<dim3(8,2,1), 512, LSTM_SMEM_FLOATS * (int)sizeof(float)>>>(whh_f, whh_b);

    // q and k in one launch
    {
        SPair p = { p_ctx, p_ctx, wq, wk, bq, bk, p_q, p_k };
        sgemm_kernel<<<dim3(8,8,2), 256>>>(p, HD2, HD2, HD2, HD2, 1<<30);
    }

    attn_kernel<<<NROWS, 128>>>();

    // hop 0 logits (factorized): a = ctx2[:, :512].cls_wL + cb ; v = ctx2[:, 512:].cls_wR
    proj_dual_kernel<<<NROWS, 384>>>(p_ctx2, HD2, 0, HD2, p_ctx2, HD2, 512, HD2, cls_w, cls_b);

    for (int hop = 0; hop < 2; hop++) {
        lm_kernel<<<NB*CN, 128>>>();
        aug_kernel<<<NROWS, 256>>>(hop);
        // stacked feat GEMM: [FR;FC] = [augR;augC] @ fw^T, bias only on FR rows
        SPair p = { p_aug, p_aug, p_fwpad, p_fwpad, feat_b, feat_b, p_F, p_F };
        sgemm_kernel<<<dim3(16,16,1), 256>>>(p, AUGW, AUGW, HD4, AUGW, NROWS);
        proj_dual_kernel<<<NROWS, 384>>>(p_F, HD4, 0, HD4, p_F + (size_t)NROWS*HD4, HD4, 0, HD4,
                                         cls_w, cls_b);
    }

    out_kernel<<<NROWS, LL*CN>>>(out);
}

// round 7
// speedup vs baseline: 2.0478x; 1.8847x over previous
#include <cuda_runtime.h>
#include <cuda_bf16.h>
#include <cstdint>
#include <math.h>

// ---------------- problem sizes ----------------
#define NB 4
#define LL 128
#define HH 256
#define HD2 512
#define HD4 1024
#define CN 6
#define EMBD 400
#define GEND 300
#define NROWS 512            // B*L
#define AUGW 1056            // 4H + 3C = 1042, padded to multiple of 16

// ---------------- scratch (no cudaMalloc allowed) ----------------
__device__ float g_emb[NROWS*EMBD];
__device__ float g_bsumf[HD4];
__device__ float g_bsumb[HD4];
__device__ float g_gxf[NROWS*HD4];
__device__ float g_gxb[NROWS*HD4];
__device__ float g_ctx[NROWS*HD2];
__device__ float g_q[NROWS*HD2];
__device__ float g_k[NROWS*HD2];
__device__ float g_ctx2[NROWS*HD2];
__device__ float g_a[NROWS*CN];
__device__ float g_v[NROWS*CN];
__device__ float g_lm[NROWS*CN];
__device__ float g_aug[2*NROWS*AUGW];    // [augR ; augC]
__device__ float g_F[2*NROWS*HD4];       // [FR ; FC]
__device__ float g_fwpad[HD4*AUGW];

__device__ __forceinline__ float sigmoidf_(float x) { return 1.f / (1.f + expf(-x)); }

__device__ __forceinline__ uint32_t smem_u32_(const void* p) {
    uint32_t a;
    asm("{ .reg .u64 t; cvta.to.shared.u64 t, %1; cvt.u32.u64 %0, t; }" : "=r"(a) : "l"(p));
    return a;
}
__device__ __forceinline__ void st_dsmem_f32_(uint32_t saddr, int rank, float v) {
    uint32_t ra;
    asm volatile("mapa.shared::cluster.u32 %0, %1, %2;" : "=r"(ra) : "r"(saddr), "r"(rank));
    asm volatile("st.shared::cluster.f32 [%0], %1;" :: "r"(ra), "f"(v) : "memory");
}
__device__ __forceinline__ void cluster_sync_() {
    asm volatile("barrier.cluster.arrive.aligned;" ::: "memory");
    asm volatile("barrier.cluster.wait.aligned;" ::: "memory");
}

// ---------------- tiny prep kernels ----------------
__global__ void bias_sum_kernel(const float* __restrict__ bihf, const float* __restrict__ bhhf,
                                const float* __restrict__ bihb, const float* __restrict__ bhhb) {
    int i = blockIdx.x * blockDim.x + threadIdx.x;
    if (i < HD4) {
        g_bsumf[i] = bihf[i] + bhhf[i];
        g_bsumb[i] = bihb[i] + bhhb[i];
    }
}

__global__ void fwpad_kernel(const float* __restrict__ feat_w) {
    int n = blockIdx.x;
    for (int k = threadIdx.x; k < AUGW; k += blockDim.x)
        g_fwpad[n*AUGW + k] = (k < 1042) ? feat_w[n*1042 + k] : 0.f;
}

__global__ void embed_kernel(const int* __restrict__ tok, const float* __restrict__ mask,
                             const float* __restrict__ gen, const float* __restrict__ dom) {
    int r = blockIdx.x;
    int t = tok[r];
    float m = mask[r];
    const float* gp = gen + (size_t)t * GEND;
    const float* dp = dom + (size_t)t * (EMBD - GEND);
    for (int d = threadIdx.x; d < EMBD; d += blockDim.x)
        g_emb[r*EMBD + d] = m * (d < GEND ? gp[d] : dp[d - GEND]);
}

// ---------------- fp32 GEMM with pointer-pair batching + reg prefetch ----------------
struct SPair {
    const float* A0; const float* A1;
    const float* W0; const float* W1;
    const float* b0; const float* b1;
    float* C0; float* C1;
};

__launch_bounds__(256)
__global__ void sgemm_kernel(SPair p, int lda, int ldw, int ldc, int K, int biasLimit) {
    const float* __restrict__ A    = blockIdx.z ? p.A1 : p.A0;
    const float* __restrict__ W    = blockIdx.z ? p.W1 : p.W0;
    const float* __restrict__ bias = blockIdx.z ? p.b1 : p.b0;
    float* __restrict__ C          = blockIdx.z ? p.C1 : p.C0;
    __shared__ float As[16][68];
    __shared__ float Bs[16][68];
    const int tid = threadIdx.x;
    const int tx = tid & 15, ty = tid >> 4;
    const int m0 = blockIdx.x * 64, n0 = blockIdx.y * 64;

    int lmm[4], lkk[4];
#pragma unroll
    for (int i = 0; i < 4; i++) { int idx = tid + i * 256; lmm[i] = idx >> 4; lkk[i] = idx & 15; }

    float pa[4], pb[4];
#pragma unroll
    for (int i = 0; i < 4; i++) {
        pa[i] = A[(size_t)(m0 + lmm[i]) * lda + lkk[i]];
        pb[i] = W[(size_t)(n0 + lmm[i]) * ldw + lkk[i]];
    }

    float acc[4][4];
#pragma unroll
    for (int i = 0; i < 4; i++)
#pragma unroll
        for (int j = 0; j < 4; j++) acc[i][j] = 0.f;

    for (int k0 = 0; k0 < K; k0 += 16) {
        __syncthreads();
#pragma unroll
        for (int i = 0; i < 4; i++) {
            As[lkk[i]][lmm[i]] = pa[i];
            Bs[lkk[i]][lmm[i]] = pb[i];
        }
        __syncthreads();
        if (k0 + 16 < K) {
#pragma unroll
            for (int i = 0; i < 4; i++) {
                pa[i] = A[(size_t)(m0 + lmm[i]) * lda + k0 + 16 + lkk[i]];
                pb[i] = W[(size_t)(n0 + lmm[i]) * ldw + k0 + 16 + lkk[i]];
            }
        }
#pragma unroll
        for (int kk = 0; kk < 16; kk++) {
            float4 a4 = *(const float4*)&As[kk][ty * 4];
            float4 b4 = *(const float4*)&Bs[kk][tx * 4];
            float av[4] = {a4.x, a4.y, a4.z, a4.w};
            float bv[4] = {b4.x, b4.y, b4.z, b4.w};
#pragma unroll
            for (int i = 0; i < 4; i++)
#pragma unroll
                for (int j = 0; j < 4; j++)
                    acc[i][j] = fmaf(av[i], bv[j], acc[i][j]);
        }
    }
#pragma unroll
    for (int i = 0; i < 4; i++) {
        int m = m0 + ty * 4 + i;
        float4 o = make_float4(acc[i][0], acc[i][1], acc[i][2], acc[i][3]);
        if (bias && m < biasLimit) {
            const float* bp = bias + n0 + tx * 4;
            o.x += bp[0]; o.y += bp[1]; o.z += bp[2]; o.w += bp[3];
        }
        *(float4*)&C[(size_t)m * ldc + n0 + tx * 4] = o;
    }
}

// ---------------- BiLSTM v2: 8 clusters of 8 CTAs, one cluster per (dir,batch) ----
// grid (8, 8): blockIdx.x = cluster rank, blockIdx.y = dir*4 + batch.
// CTA owns 128 gate rows (32 units x 4 gates) for ONE batch. whh slice lives in
// REGISTERS (64 floats/thread: thread (lr, ks) holds whh[grow][ks*64..+64]).
// h (256 floats) is in smem, read as warp-uniform broadcast LDS.128 -> near-zero
// smem bandwidth. Per step: 64 FFMA/thread, 4-way K-slice reduce, nonlinearity on
// 32 threads (c in registers), h pushed to all 8 ranks via DSMEM, cluster.sync.
__global__ void __launch_bounds__(512, 1) __cluster_dims__(8, 1, 1)
lstm_kernel(const float* __restrict__ whh_f, const float* __restrict__ whh_b) {
    __shared__ float hsh[2][256];
    __shared__ float part[4][128];
    const int rank = blockIdx.x;
    const int db   = blockIdx.y;
    const int dir  = db >> 2;
    const int b    = db & 3;
    const int base = rank * 32;
    const float* __restrict__ whh = dir ? whh_b : whh_f;
    const float* __restrict__ gx  = dir ? g_gxb : g_gxf;
    const int tid = threadIdx.x;
    const int lr  = tid & 127;            // local gate row
    const int ks  = tid >> 7;             // K-slice 0..3
    const int grow = ((lr >> 5) << 8) + base + (lr & 31);  // global gate row

    // one-time: load W slice into registers
    float Wreg[64];
    {
        const float4* wrow = (const float4*)(whh + (size_t)grow * 256 + ks * 64);
#pragma unroll
        for (int j = 0; j < 16; j++) {
            float4 w = wrow[j];
            Wreg[4*j]   = w.x; Wreg[4*j+1] = w.y;
            Wreg[4*j+2] = w.z; Wreg[4*j+3] = w.w;
        }
    }
    if (tid < 256) { hsh[0][tid] = 0.f; hsh[1][tid] = 0.f; }
    float c = 0.f;                        // threads 0..31: cell state for unit tid
    const uint32_t h_sa0 = smem_u32_(&hsh[0][base]);
    const uint32_t h_sa1 = smem_u32_(&hsh[1][base]);
    __syncthreads();
    cluster_sync_();

    int par = 0;
    for (int step = 0; step < 128; step++) {
        const int pos = dir ? (127 - step) : step;
        // prefetch gx for this (b,pos) row (L2 hit; issued before the FFMA block)
        float gxv = 0.f;
        if (tid < 128) gxv = __ldg(&gx[((size_t)((b << 7) + pos) << 10) + grow]);

        const float4* h4 = (const float4*)&hsh[par][ks * 64];
        float acc = 0.f;
#pragma unroll
        for (int j = 0; j < 16; j++) {
            float4 hv = h4[j];               // warp-uniform broadcast
            acc = fmaf(Wreg[4*j],   hv.x, acc);
            acc = fmaf(Wreg[4*j+1], hv.y, acc);
            acc = fmaf(Wreg[4*j+2], hv.z, acc);
            acc = fmaf(Wreg[4*j+3], hv.w, acc);
        }
        part[ks][lr] = acc;
        __syncthreads();

        if (tid < 128) {
            float g = part[0][tid] + part[1][tid] + part[2][tid] + part[3][tid] + gxv;
            part[0][tid] = g;                // gate value, indexed by lr
        }
        __syncthreads();

        if (tid < 32) {
            float gi = part[0][tid];
            float gf = part[0][32 + tid];
            float gg = part[0][64 + tid];
            float go = part[0][96 + tid];
            c = sigmoidf_(gf) * c + sigmoidf_(gi) * tanhf(gg);
            float h = sigmoidf_(go) * tanhf(c);
            g_ctx[(((size_t)((b << 7) + pos)) << 9) + (dir << 8) + base + tid] = h;
            uint32_t off = (par ? h_sa0 : h_sa1) + tid * 4u;   // next-parity buffer
#pragma unroll
            for (int rd = 0; rd < 8; rd++)
                st_dsmem_f32_(off, rd, h);
        }
        cluster_sync_();
        par ^= 1;
    }
}

// ---------------- fused attention: scores + softmax + AV + residual ----------------
__global__ void __launch_bounds__(128)
attn_kernel() {
    int r = blockIdx.x, b = r >> 7, t = threadIdx.x;
    __shared__ float qs[512];
    __shared__ float sc[128];
    __shared__ float red[128];
    const float* qrow = g_q + (size_t)r * HD2;
    for (int k = t; k < 512; k += 128) qs[k] = qrow[k];
    __syncthreads();

    const float4* kr = (const float4*)(g_k + ((size_t)((b << 7) + t)) * HD2);
    const float4* q4 = (const float4*)qs;
    float s0 = 0.f, s1 = 0.f, s2 = 0.f, s3 = 0.f;
#pragma unroll 8
    for (int k = 0; k < 128; k++) {
        float4 kv = kr[k], qv = q4[k];
        s0 = fmaf(qv.x, kv.x, s0);
        s1 = fmaf(qv.y, kv.y, s1);
        s2 = fmaf(qv.z, kv.z, s2);
        s3 = fmaf(qv.w, kv.w, s3);
    }
    float s = (s0 + s1) + (s2 + s3);

    red[t] = s; __syncthreads();
    for (int off = 64; off; off >>= 1) { if (t < off) red[t] = fmaxf(red[t], red[t + off]); __syncthreads(); }
    float mx = red[0]; __syncthreads();
    float e = expf(s - mx);
    red[t] = e; __syncthreads();
    for (int off = 64; off; off >>= 1) { if (t < off) red[t] += red[t + off]; __syncthreads(); }
    sc[t] = e / red[0];
    __syncthreads();

    float a0 = 0.f, a1 = 0.f, a2 = 0.f, a3 = 0.f;
    for (int j = 0; j < 128; j++) {
        float a = sc[j];
        const float* cr = g_ctx + ((size_t)((b << 7) + j)) * HD2;
        a0 = fmaf(a, cr[t],       a0);
        a1 = fmaf(a, cr[t + 128], a1);
        a2 = fmaf(a, cr[t + 256], a2);
        a3 = fmaf(a, cr[t + 384], a3);
    }
    const float* crr = g_ctx + ((size_t)r) * HD2;
    float* o = g_ctx2 + ((size_t)r) * HD2;
    o[t]       = crr[t]       + a0;
    o[t + 128] = crr[t + 128] + a1;
    o[t + 256] = crr[t + 256] + a2;
    o[t + 384] = crr[t + 384] + a3;
}

// ---------------- dual class projection ----------------
__global__ void __launch_bounds__(384)
proj_dual_kernel(const float* __restrict__ Xa, int ldxa, int offA, int Ka,
                 const float* __restrict__ Xv, int ldxv, int offV, int Kv,
                 const float* __restrict__ cw, const float* __restrict__ cb) {
    int r = blockIdx.x;
    int tid = threadIdx.x;
    int half = tid / 192;
    int t = tid % 192;
    int c = t >> 5, l = t & 31;
    const float* X = half ? (Xv + (size_t)r * ldxv) : (Xa + (size_t)r * ldxa);
    const float* wr = cw + c * 1024 + (half ? offV : offA);
    int K = half ? Kv : Ka;
    float acc = 0.f;
    for (int k = l; k < K; k += 32) acc = fmaf(X[k], wr[k], acc);
#pragma unroll
    for (int off = 16; off; off >>= 1) acc += __shfl_xor_sync(0xffffffffu, acc, off);
    if (l == 0) {
        if (half) g_v[r*CN + c] = acc;
        else      g_a[r*CN + c] = acc + cb[c];
    }
}

// ---------------- lm scan: prefix/suffix max per (b,c) ----------------
__global__ void lm_kernel() {
    __shared__ float sa[128], sv[128], pa[128], sf[128];
    int t = threadIdx.x;
    int b = blockIdx.x / CN, c = blockIdx.x % CN;
    float av = g_a[((b << 7) + t)*CN + c];
    float vv = g_v[((b << 7) + t)*CN + c];
    sa[t] = av; sv[t] = vv; pa[t] = av; sf[t] = vv;
    __syncthreads();
    for (int off = 1; off < 128; off <<= 1) {
        float nx = pa[t]; if (t >= off) nx = fmaxf(nx, pa[t - off]);
        float ny = sf[t]; if (t + off < 128) ny = fmaxf(ny, sf[t + off]);
        __syncthreads();
        pa[t] = nx; sf[t] = ny;
        __syncthreads();
    }
    float lm = fmaxf(fmaxf(pa[t] + sv[t], sa[t] + sf[t]), 0.f);
    g_lm[((b << 7) + t)*CN + c] = lm;
}

// ---------------- build augmented GEMM inputs (stacked [augR;augC]) ----------------
__global__ void aug_kernel(int mode) {
    int r = blockIdx.x;
    float* AR = g_aug + (size_t)r * AUGW;
    float* AC = g_aug + (size_t)(NROWS + r) * AUGW;
    const float* lm = g_lm + r*CN;
    const float* aa = g_a  + r*CN;
    const float* vv = g_v  + r*CN;
    for (int k = threadIdx.x; k < AUGW; k += blockDim.x) {
        float rv = 0.f, cv = 0.f;
        if (k < 1024) {
            if (mode == 0) {
                if (k < 512) rv = g_ctx2[(size_t)r*512 + k];
                else         cv = g_ctx2[(size_t)r*512 + k - 512];
            } else {
                rv = g_F[(size_t)r*1024 + k];
                cv = g_F[(size_t)(NROWS + r)*1024 + k];
            }
        } else if (k < 1030) { rv = lm[k - 1024]; }
        else if (k < 1036)   { cv = lm[k - 1030]; }
        else if (k < 1042)   { rv = aa[k - 1036]; cv = vv[k - 1036]; }
        AR[k] = rv; AC[k] = cv;
    }
}

// ---------------- final output: out[b,i,j,c] = a[b,i,c] + v[b,j,c] ----------------
__global__ void out_kernel(float* __restrict__ out) {
    int r = blockIdx.x;
    int b = r >> 7;
    int t = threadIdx.x;           // 768 = 128*6
    int j = t / CN, c = t % CN;
    out[((size_t)r * 128 + j)*CN + c] = g_a[r*CN + c] + g_v[((b << 7) + j)*CN + c];
}

// ---------------- launcher ----------------
extern "C" void kernel_launch(void* const* d_in, const int* in_sizes, int n_in,
                              void* d_out, int out_size) {
    (void)in_sizes; (void)n_in; (void)out_size;
    const int*   tok    = (const int*)  d_in[0];
    const float* mask   = (const float*)d_in[2];
    const float* gen    = (const float*)d_in[3];
    const float* dom    = (const float*)d_in[4];
    const float* wih_f  = (const float*)d_in[5];
    const float* whh_f  = (const float*)d_in[6];
    const float* bih_f  = (const float*)d_in[7];
    const float* bhh_f  = (const float*)d_in[8];
    const float* wih_b  = (const float*)d_in[9];
    const float* whh_b  = (const float*)d_in[10];
    const float* bih_b  = (const float*)d_in[11];
    const float* bhh_b  = (const float*)d_in[12];
    const float* wq     = (const float*)d_in[13];
    const float* bq     = (const float*)d_in[14];
    const float* wk     = (const float*)d_in[15];
    const float* bk     = (const float*)d_in[16];
    const float* feat_w = (const float*)d_in[17];
    const float* feat_b = (const float*)d_in[18];
    const float* cls_w  = (const float*)d_in[19];
    const float* cls_b  = (const float*)d_in[20];
    float* out = (float*)d_out;

    float *p_emb, *p_bsumf, *p_bsumb, *p_gxf, *p_gxb, *p_ctx, *p_q, *p_k,
          *p_ctx2, *p_aug, *p_F, *p_fwpad;
    cudaGetSymbolAddress((void**)&p_emb,    g_emb);
    cudaGetSymbolAddress((void**)&p_bsumf,  g_bsumf);
    cudaGetSymbolAddress((void**)&p_bsumb,  g_bsumb);
    cudaGetSymbolAddress((void**)&p_gxf,    g_gxf);
    cudaGetSymbolAddress((void**)&p_gxb,    g_gxb);
    cudaGetSymbolAddress((void**)&p_ctx,    g_ctx);
    cudaGetSymbolAddress((void**)&p_q,      g_q);
    cudaGetSymbolAddress((void**)&p_k,      g_k);
    cudaGetSymbolAddress((void**)&p_ctx2,   g_ctx2);
    cudaGetSymbolAddress((void**)&p_aug,    g_aug);
    cudaGetSymbolAddress((void**)&p_F,      g_F);
    cudaGetSymbolAddress((void**)&p_fwpad,  g_fwpad);

    bias_sum_kernel<<<4, 256>>>(bih_f, bhh_f, bih_b, bhh_b);
    fwpad_kernel<<<HD4, 256>>>(feat_w);
    embed_kernel<<<NROWS, 128>>>(tok, mask, gen, dom);

    // gx_f and gx_b in one launch: C = emb @ wih^T + (bih+bhh)
    {
        SPair p = { p_emb, p_emb, wih_f, wih_b, p_bsumf, p_bsumb, p_gxf, p_gxb };
        sgemm_kernel<<<dim3(8,16,2), 256>>>(p, EMBD, EMBD, HD4, EMBD, 1<<30);
    }

    // BiLSTM: 8 clusters (one per dir x batch) of 8 CTAs each
    lstm_kernel<<<dim3(8,8,1), 512>>>(whh_f, whh_b);

    // q and k in one launch
    {
        SPair p = { p_ctx, p_ctx, wq, wk, bq, bk, p_q, p_k };
        sgemm_kernel<<<dim3(8,8,2), 256>>>(p, HD2, HD2, HD2, HD2, 1<<30);
    }

    attn_kernel<<<NROWS, 128>>>();

    // hop 0 logits (factorized)
    proj_dual_kernel<<<NROWS, 384>>>(p_ctx2, HD2, 0, HD2, p_ctx2, HD2, 512, HD2, cls_w, cls_b);

    for (int hop = 0; hop < 2; hop++) {
        lm_kernel<<<NB*CN, 128>>>();
        aug_kernel<<<NROWS, 256>>>(hop);
        SPair p = { p_aug, p_aug, p_fwpad, p_fwpad, feat_b, feat_b, p_F, p_F };
        sgemm_kernel<<<dim3(16,16,1), 256>>>(p, AUGW, AUGW, HD4, AUGW, NROWS);
        proj_dual_kernel<<<NROWS, 384>>>(p_F, HD4, 0, HD4, p_F + (size_t)NROWS*HD4, HD4, 0, HD4,
                                         cls_w, cls_b);
    }

    out_kernel<<<NROWS, LL*CN>>>(out);
}